// round 1
// baseline (speedup 1.0000x reference)
#include <cuda_runtime.h>
#include <cstdint>

// mean_aggregator: out[b, :] = (1/32) * sum_{s<32} emb[neighbors[b,s], :]
// B=50000, S=32, D=128. neighbors int32 [B,S], emb float32 [500000,128].
//
// One warp per output row. Lane s holds neighbor id s (coalesced index load),
// broadcast via shfl; each lane accumulates one float4 (4 dims) so each
// gathered row is a single fully-coalesced 512B transaction across the warp.

#ifndef WARPS_PER_BLOCK
#define WARPS_PER_BLOCK 8
#endif

__global__ __launch_bounds__(WARPS_PER_BLOCK * 32)
void mean_agg_kernel(const int* __restrict__ neighbors,
                     const float4* __restrict__ emb,   // [num_nodes, 32] float4
                     float4* __restrict__ out,         // [batch, 32] float4
                     int batch)
{
    const int warp = (blockIdx.x * blockDim.x + threadIdx.x) >> 5;
    const int lane = threadIdx.x & 31;
    if (warp >= batch) return;

    // Coalesced load of this row's 32 neighbor ids (one per lane).
    const int my_nbr = neighbors[warp * 32 + lane];

    float4 acc = make_float4(0.f, 0.f, 0.f, 0.f);

    #pragma unroll
    for (int s = 0; s < 32; ++s) {
        const int n = __shfl_sync(0xffffffffu, my_nbr, s);
        const float4 v = __ldg(&emb[(size_t)n * 32 + lane]);
        acc.x += v.x;
        acc.y += v.y;
        acc.z += v.z;
        acc.w += v.w;
    }

    const float inv = 1.0f / 32.0f;
    acc.x *= inv; acc.y *= inv; acc.z *= inv; acc.w *= inv;

    out[(size_t)warp * 32 + lane] = acc;
}

extern "C" void kernel_launch(void* const* d_in, const int* in_sizes, int n_in,
                              void* d_out, int out_size)
{
    const int* neighbors = (const int*)d_in[0];          // [B, 32] int32
    const float4* emb    = (const float4*)d_in[1];       // [N, 128] f32 as [N,32] float4

    const int batch = in_sizes[0] / 32;                  // 50000

    const int threads = WARPS_PER_BLOCK * 32;
    const int warps_needed = batch;
    const int blocks = (warps_needed + WARPS_PER_BLOCK - 1) / WARPS_PER_BLOCK;

    mean_agg_kernel<<<blocks, threads>>>(neighbors, emb, (float4*)d_out, batch);
}